// round 1
// baseline (speedup 1.0000x reference)
#include <cuda_runtime.h>
#include <cstdint>

#define N_NODES 2048
#define HID 1024
#define LDQ 1026          // Wq row stride (HID + 2)
#define T_STEPS 2304      // N + N/8
#define TOUR_LEN 2305
#define COEF 0.015625f    // ALPHA / sqrt(HID) = 0.5/32, exact power of two

// Scratch (allocation-free rule: __device__ globals)
static __device__ float g_K[N_NODES * HID];      // 8 MB
static __device__ float g_A[N_NODES * HID];      // 8 MB
static __device__ float g_P[N_NODES * N_NODES];  // 16 MB  P[last][cand]
static __device__ float g_v[N_NODES];
static __device__ float g_w[N_NODES];

// ---------------------------------------------------------------------------
// fp32 SIMT GEMM, 128x128x16 tile, 256 threads, 8x8 per-thread microtile.
// C[m,n] = scale * sum_k A[m,k] * (BT ? B[n,k] : B[k,n])  (+ bias[n])
// All of M, N multiples of 128; Kd multiple of 16 (true for our shapes).
// ---------------------------------------------------------------------------
template <bool BT, bool HAS_BIAS>
__global__ __launch_bounds__(256)
void gemm128(const float* __restrict__ A, const float* __restrict__ B,
             const float* __restrict__ bias, float* __restrict__ C,
             int Kd, int lda, int ldb, int ldc, float scale)
{
    __shared__ float As[16][128];
    __shared__ float Bs[16][128];
    const int tid = threadIdx.x;
    const int bm = blockIdx.y * 128, bn = blockIdx.x * 128;
    const int tx = tid & 15, ty = tid >> 4;

    float acc[8][8];
#pragma unroll
    for (int i = 0; i < 8; i++)
#pragma unroll
        for (int j = 0; j < 8; j++) acc[i][j] = 0.f;

    const int ar  = tid >> 2;   // 0..63 (row within half-tile)
    const int ac4 = tid & 3;    // float4 slot within 16-wide k
    const float* Ap  = A + (size_t)(bm + ar) * lda + ac4 * 4;
    const float* Bpt = BT ? (B + (size_t)(bn + ar) * ldb + ac4 * 4) : B;
    const int br  = tid >> 6;   // 0..3
    const int bc2 = tid & 63;   // float2 slot within 128-wide n
    const float* Bpn = BT ? B : (B + (size_t)br * ldb + bn + bc2 * 2);

    for (int k0 = 0; k0 < Kd; k0 += 16) {
#pragma unroll
        for (int p = 0; p < 2; p++) {
            float4 a = *(const float4*)(Ap + (size_t)p * 64 * lda + k0);
            int r = ar + p * 64;
            As[ac4 * 4 + 0][r] = a.x; As[ac4 * 4 + 1][r] = a.y;
            As[ac4 * 4 + 2][r] = a.z; As[ac4 * 4 + 3][r] = a.w;
        }
        if (BT) {
#pragma unroll
            for (int p = 0; p < 2; p++) {
                float4 b = *(const float4*)(Bpt + (size_t)p * 64 * ldb + k0);
                int r = ar + p * 64;
                Bs[ac4 * 4 + 0][r] = b.x; Bs[ac4 * 4 + 1][r] = b.y;
                Bs[ac4 * 4 + 2][r] = b.z; Bs[ac4 * 4 + 3][r] = b.w;
            }
        } else {
            // NN path: B row stride may be odd*float2 (ldb=1026) -> float2 loads
#pragma unroll
            for (int p = 0; p < 4; p++) {
                float2 b = *(const float2*)(Bpn + (size_t)(k0 + p * 4) * ldb);
                Bs[br + p * 4][bc2 * 2 + 0] = b.x;
                Bs[br + p * 4][bc2 * 2 + 1] = b.y;
            }
        }
        __syncthreads();
#pragma unroll
        for (int kk = 0; kk < 16; kk++) {
            float a[8], b[8];
            *(float4*)&a[0] = *(const float4*)&As[kk][ty * 8];
            *(float4*)&a[4] = *(const float4*)&As[kk][ty * 8 + 4];
            *(float4*)&b[0] = *(const float4*)&Bs[kk][tx * 8];
            *(float4*)&b[4] = *(const float4*)&Bs[kk][tx * 8 + 4];
#pragma unroll
            for (int i = 0; i < 8; i++)
#pragma unroll
                for (int j = 0; j < 8; j++)
                    acc[i][j] = fmaf(a[i], b[j], acc[i][j]);
        }
        __syncthreads();
    }
#pragma unroll
    for (int i = 0; i < 8; i++) {
        int row = bm + ty * 8 + i;
#pragma unroll
        for (int j = 0; j < 8; j += 4) {
            int col = bn + tx * 8 + j;
            float4 o;
            o.x = acc[i][j + 0] * scale;
            o.y = acc[i][j + 1] * scale;
            o.z = acc[i][j + 2] * scale;
            o.w = acc[i][j + 3] * scale;
            if (HAS_BIAS) {
                o.x += bias[col + 0]; o.y += bias[col + 1];
                o.z += bias[col + 2]; o.w += bias[col + 3];
            }
            *(float4*)(C + (size_t)row * ldc + col) = o;
        }
    }
}

// ---------------------------------------------------------------------------
// v[i] = c * sum_h K[i,h]*Wq[h,1024];  w[i] = c * sum_h K[i,h]*bq[h]
// 256 threads/block, warp per row, 8 rows/block, 256 blocks.
// ---------------------------------------------------------------------------
__global__ __launch_bounds__(256)
void vw_kernel(const float* __restrict__ Wq, const float* __restrict__ bq)
{
    __shared__ float scol[HID];
    __shared__ float sbq[HID];
    const int tid = threadIdx.x;
    for (int h = tid; h < HID; h += 256) {
        scol[h] = Wq[(size_t)h * LDQ + HID];  // Wq[:,1024] (the load/cap column)
        sbq[h]  = bq[h];
    }
    __syncthreads();
    const int warp = tid >> 5, lane = tid & 31;
    const int row = blockIdx.x * 8 + warp;
    const float* Kr = g_K + (size_t)row * HID;
    float vv = 0.f, ww = 0.f;
#pragma unroll 4
    for (int m = 0; m < HID / 32; m++) {
        int h = lane + m * 32;
        float k = Kr[h];
        vv = fmaf(k, scol[h], vv);
        ww = fmaf(k, sbq[h], ww);
    }
#pragma unroll
    for (int off = 16; off; off >>= 1) {
        vv += __shfl_xor_sync(0xffffffffu, vv, off);
        ww += __shfl_xor_sync(0xffffffffu, ww, off);
    }
    if (lane == 0) { g_v[row] = COEF * vv; g_w[row] = COEF * ww; }
}

// ---------------------------------------------------------------------------
// Sequential decoder: single block, 256 threads, 8 candidates/thread.
// Per step: s_i = P[last,i] + u*v_i + w_i ; masked argmax (first-index ties).
// ---------------------------------------------------------------------------
__global__ __launch_bounds__(256)
void decode_kernel(const float* __restrict__ demands,
                   const int* __restrict__ cap_ptr,
                   const int* __restrict__ depot_ptr,
                   float* __restrict__ out)
{
    __shared__ float sdem[N_NODES];
    __shared__ float sv[N_NODES];
    __shared__ float sw[N_NODES];
    __shared__ unsigned char svis[N_NODES / 8];
    __shared__ float red_v[8];
    __shared__ int   red_i[8];
    __shared__ int   sh_last, sh_count, sh_done, sh_depot;
    __shared__ float sh_load, sh_cap;

    const float NEG_INF = __int_as_float(0xff800000u);
    const int tid = threadIdx.x;

    for (int i = tid; i < N_NODES; i += 256) {
        sdem[i] = demands[i];
        sv[i]   = g_v[i];
        sw[i]   = g_w[i];
    }
    svis[tid] = 0;
    __syncthreads();
    if (tid == 0) {
        int ci = cap_ptr ? cap_ptr[0] : 40;
        // robust: tolerate int32/int64 (low word) or raw float32 bits
        float capf = (ci >= 0 && ci < (1 << 23)) ? (float)ci : __int_as_float(ci);
        int dep = depot_ptr ? depot_ptr[0] : 0;
        if (dep < 0 || dep >= N_NODES) dep = 0;
        sh_cap = capf; sh_depot = dep;
        sh_last = dep; sh_load = capf; sh_count = 1; sh_done = 0;
        svis[dep >> 3] = (unsigned char)(1u << (dep & 7));
        out[0] = (float)dep;
    }
    __syncthreads();

    const int lane = tid & 31, warp = tid >> 5;
    int tstop = T_STEPS;

    for (int t = 0; t < T_STEPS; t++) {
        const int   last = sh_last;
        const float load = sh_load;
        const float u    = load / sh_cap;
        const int base = tid * 8;
        const float* Pr = g_P + (size_t)last * N_NODES + base;
        float4 p0 = __ldg((const float4*)Pr);
        float4 p1 = __ldg((const float4*)(Pr + 4));
        const unsigned vb = svis[tid];
        float pv[8] = {p0.x, p0.y, p0.z, p0.w, p1.x, p1.y, p1.z, p1.w};

        float bestv = NEG_INF;
        int   besti = base;
#pragma unroll
        for (int j = 0; j < 8; j++) {
            int idx = base + j;
            float s = fmaf(u, sv[idx], pv[j] + sw[idx]);
            bool feas = !((vb >> j) & 1u) && (sdem[idx] <= load);
            float sm = feas ? s : NEG_INF;
            if (sm > bestv) { bestv = sm; besti = idx; }   // strict > => first max
        }
#pragma unroll
        for (int off = 16; off; off >>= 1) {
            float ov = __shfl_down_sync(0xffffffffu, bestv, off);
            int   oi = __shfl_down_sync(0xffffffffu, besti, off);
            if (ov > bestv || (ov == bestv && oi < besti)) { bestv = ov; besti = oi; }
        }
        if (lane == 0) { red_v[warp] = bestv; red_i[warp] = besti; }
        __syncthreads();
        if (tid == 0) {
            float bv = red_v[0]; int bi = red_i[0];
#pragma unroll
            for (int wI = 1; wI < 8; wI++) {
                float ov = red_v[wI]; int oi = red_i[wI];
                if (ov > bv || (ov == bv && oi < bi)) { bv = ov; bi = oi; }
            }
            if (bv > NEG_INF) {                 // has feasible candidate -> take
                out[1 + t]        = (float)bi;
                out[TOUR_LEN + t] = bv;         // s[cand] (mask==identity at cand)
                svis[bi >> 3] |= (unsigned char)(1u << (bi & 7));
                sh_load = load - sdem[bi];
                sh_last = bi;
                sh_count = sh_count + 1;
            } else {                            // route end / padding step
                out[1 + t]        = (float)sh_depot;
                out[TOUR_LEN + t] = 0.0f;
                sh_load = sh_cap;
                sh_last = sh_depot;
                if (sh_count == N_NODES) sh_done = 1;
            }
        }
        __syncthreads();
        if (sh_done) { tstop = t + 1; break; }
    }
    // Padding after 'done': every remaining step emits (depot, 0)
    for (int t2 = tstop + tid; t2 < T_STEPS; t2 += 256) {
        out[1 + t2]        = (float)sh_depot;
        out[TOUR_LEN + t2] = 0.0f;
    }
}

// ---------------------------------------------------------------------------
extern "C" void kernel_launch(void* const* d_in, const int* in_sizes, int n_in,
                              void* d_out, int out_size)
{
    const float* node_emb = (const float*)d_in[0];
    const float* demands  = (const float*)d_in[1];
    const float* Wq       = (const float*)d_in[2];
    const float* bq       = (const float*)d_in[3];
    const float* Wk       = (const float*)d_in[4];
    const float* bk       = (const float*)d_in[5];
    const int* capi = (n_in > 6) ? (const int*)d_in[6] : nullptr;
    const int* depi = (n_in > 7) ? (const int*)d_in[7] : nullptr;
    float* out = (float*)d_out;

    float *pK = nullptr, *pA = nullptr, *pP = nullptr;
    cudaGetSymbolAddress((void**)&pK, g_K);
    cudaGetSymbolAddress((void**)&pA, g_A);
    cudaGetSymbolAddress((void**)&pP, g_P);

    dim3 blk(256);
    // K = node_emb @ Wk^T + bk          [2048,1024]
    gemm128<true, true><<<dim3(HID / 128, N_NODES / 128), blk>>>(
        node_emb, Wk, bk, pK, HID, HID, HID, HID, 1.0f);
    // A = K @ Wq[:, :1024]              [2048,1024]
    gemm128<false, false><<<dim3(HID / 128, N_NODES / 128), blk>>>(
        pK, Wq, nullptr, pA, HID, HID, LDQ, HID, 1.0f);
    // P = c * node_emb @ A^T            [2048(last), 2048(cand)]
    gemm128<true, false><<<dim3(N_NODES / 128, N_NODES / 128), blk>>>(
        node_emb, pA, nullptr, pP, HID, HID, HID, N_NODES, COEF);
    // v, w
    vw_kernel<<<N_NODES / 8, 256>>>(Wq, bq);
    // sequential greedy decode
    decode_kernel<<<1, 256>>>(demands, capi, depi, out);

    (void)in_sizes; (void)out_size;
}

// round 4
// speedup vs baseline: 1.3777x; 1.3777x over previous
#include <cuda_runtime.h>
#include <cstdint>

#define N_NODES 2048
#define HID 1024
#define LDQ 1026          // Wq row stride (HID + 2)
#define T_STEPS 2304      // N + N/8
#define TOUR_LEN 2305
#define COEF 0.015625f    // ALPHA / sqrt(HID) = 0.5/32, exact power of two
#define KEY_SENTINEL (-2147483647 - 1)   // INT_MIN < ordkey(-inf)=0x807FFFFF

// Scratch (allocation-free rule: __device__ globals)
static __device__ float g_K[N_NODES * HID];      // 8 MB  K = E Wk^T + bk
static __device__ float g_A[N_NODES * HID];      // 8 MB  A = K Wq1
static __device__ float g_P[N_NODES * N_NODES];  // 16 MB P[last][cand] = c*E A^T
static __device__ float g_v[N_NODES];
static __device__ float g_w[N_NODES];

// ---------------------------------------------------------------------------
// f32x2 packed helpers (FFMA2 — ptxas only emits via PTX fma.rn.f32x2).
// Per-lane IEEE fma.rn => bitwise identical to scalar fmaf chains.
// ---------------------------------------------------------------------------
__device__ __forceinline__ unsigned long long f2dup(float x) {
    unsigned long long r;
    asm("mov.b64 %0, {%1, %1};" : "=l"(r) : "f"(x));
    return r;
}
__device__ __forceinline__ void fma2(unsigned long long& d,
                                     unsigned long long a,
                                     unsigned long long b) {
    asm("fma.rn.f32x2 %0, %1, %2, %0;" : "+l"(d) : "l"(a), "l"(b));
}
__device__ __forceinline__ void f2unpack(unsigned long long v, float& lo, float& hi) {
    asm("mov.b64 {%0, %1}, %2;" : "=f"(lo), "=f"(hi) : "l"(v));
}

// Shared compute micro-kernel: 16 k-steps on buffer s, 8x8 microtile.
#define MICRO_COMPUTE(S)                                                      \
    do {                                                                      \
        _Pragma("unroll")                                                     \
        for (int kk = 0; kk < 16; kk++) {                                     \
            float4 a0 = *(const float4*)&As[S][kk][ty * 8];                   \
            float4 a1 = *(const float4*)&As[S][kk][ty * 8 + 4];               \
            ulonglong2 q0 = *(const ulonglong2*)&Bs[S][kk][tx * 8];           \
            ulonglong2 q1 = *(const ulonglong2*)&Bs[S][kk][tx * 8 + 4];       \
            float av[8] = {a0.x, a0.y, a0.z, a0.w, a1.x, a1.y, a1.z, a1.w};   \
            _Pragma("unroll")                                                 \
            for (int i = 0; i < 8; i++) {                                     \
                unsigned long long ad = f2dup(av[i]);                         \
                fma2(acc[i][0], ad, q0.x);                                    \
                fma2(acc[i][1], ad, q0.y);                                    \
                fma2(acc[i][2], ad, q1.x);                                    \
                fma2(acc[i][3], ad, q1.y);                                    \
            }                                                                 \
        }                                                                     \
    } while (0)

#define EPILOGUE()                                                            \
    do {                                                                      \
        _Pragma("unroll")                                                     \
        for (int i = 0; i < 8; i++) {                                         \
            int row = bm + ty * 8 + i;                                        \
            float o[8];                                                       \
            _Pragma("unroll")                                                 \
            for (int j = 0; j < 4; j++) f2unpack(acc[i][j], o[2*j], o[2*j+1]);\
            int col = bn + tx * 8;                                            \
            float4 o0, o1;                                                    \
            o0.x = o[0]*scale; o0.y = o[1]*scale; o0.z = o[2]*scale; o0.w = o[3]*scale; \
            o1.x = o[4]*scale; o1.y = o[5]*scale; o1.z = o[6]*scale; o1.w = o[7]*scale; \
            if (HAS_BIAS) {                                                   \
                o0.x += bias[col+0]; o0.y += bias[col+1];                     \
                o0.z += bias[col+2]; o0.w += bias[col+3];                     \
                o1.x += bias[col+4]; o1.y += bias[col+5];                     \
                o1.z += bias[col+6]; o1.w += bias[col+7];                     \
            }                                                                 \
            *(float4*)(C + (size_t)row * ldc + col)     = o0;                 \
            *(float4*)(C + (size_t)row * ldc + col + 4) = o1;                 \
        }                                                                     \
    } while (0)

// ---------------------------------------------------------------------------
// TN GEMM: C[m,n] = scale * sum_k A[m,k]*B[n,k] (+ bias[n]).
// 128x128 tile, BK=16, 256 threads, double-buffered, f32x2 accumulators.
// ---------------------------------------------------------------------------
template <bool HAS_BIAS>
__global__ __launch_bounds__(256)
void gemm_tn(const float* __restrict__ A, const float* __restrict__ B,
             const float* __restrict__ bias, float* __restrict__ C,
             int Kd, int lda, int ldb, int ldc, float scale)
{
    __shared__ __align__(16) float As[2][16][128];
    __shared__ __align__(16) float Bs[2][16][128];
    const int tid = threadIdx.x;
    const int bm = blockIdx.y * 128, bn = blockIdx.x * 128;
    const int tx = tid & 15, ty = tid >> 4;
    const int ar = tid >> 2, ac4 = tid & 3;

    unsigned long long acc[8][4];
#pragma unroll
    for (int i = 0; i < 8; i++)
#pragma unroll
        for (int j = 0; j < 4; j++) acc[i][j] = 0ull;

    const float* Ap = A + (size_t)(bm + ar) * lda + ac4 * 4;
    const float* Bp = B + (size_t)(bn + ar) * ldb + ac4 * 4;
    float4 ra0, ra1, rb0, rb1;

#define LOADT(K0)                                                             \
    do {                                                                      \
        ra0 = __ldg((const float4*)(Ap + (K0)));                              \
        ra1 = __ldg((const float4*)(Ap + (size_t)64 * lda + (K0)));           \
        rb0 = __ldg((const float4*)(Bp + (K0)));                              \
        rb1 = __ldg((const float4*)(Bp + (size_t)64 * ldb + (K0)));           \
    } while (0)
#define STORET(S)                                                             \
    do {                                                                      \
        As[S][ac4*4+0][ar] = ra0.x; As[S][ac4*4+1][ar] = ra0.y;               \
        As[S][ac4*4+2][ar] = ra0.z; As[S][ac4*4+3][ar] = ra0.w;               \
        As[S][ac4*4+0][ar+64] = ra1.x; As[S][ac4*4+1][ar+64] = ra1.y;         \
        As[S][ac4*4+2][ar+64] = ra1.z; As[S][ac4*4+3][ar+64] = ra1.w;         \
        Bs[S][ac4*4+0][ar] = rb0.x; Bs[S][ac4*4+1][ar] = rb0.y;               \
        Bs[S][ac4*4+2][ar] = rb0.z; Bs[S][ac4*4+3][ar] = rb0.w;               \
        Bs[S][ac4*4+0][ar+64] = rb1.x; Bs[S][ac4*4+1][ar+64] = rb1.y;         \
        Bs[S][ac4*4+2][ar+64] = rb1.z; Bs[S][ac4*4+3][ar+64] = rb1.w;         \
    } while (0)

    LOADT(0);
    STORET(0);
    __syncthreads();
    const int KT = Kd / 16;
#pragma unroll 1
    for (int kt = 0; kt < KT; kt++) {
        const int s = kt & 1;
        const bool more = (kt + 1) < KT;
        if (more) LOADT((kt + 1) * 16);
        MICRO_COMPUTE(s);
        if (more) { STORET(s ^ 1); __syncthreads(); }
    }
    EPILOGUE();
#undef LOADT
#undef STORET
}

// ---------------------------------------------------------------------------
// NN GEMM: C[m,n] = sum_k A[m,k]*B[k,n], B row stride ldb (=LDQ, 8B-aligned rows).
// Used for A = K @ Wq[:, :1024]. scale=1, no bias.
// ---------------------------------------------------------------------------
__global__ __launch_bounds__(256)
void gemm_nn(const float* __restrict__ A, const float* __restrict__ B,
             float* __restrict__ C, int Kd, int lda, int ldb, int ldc)
{
    __shared__ __align__(16) float As[2][16][128];
    __shared__ __align__(16) float Bs[2][16][128];
    const int tid = threadIdx.x;
    const int bm = blockIdx.y * 128, bn = blockIdx.x * 128;
    const int tx = tid & 15, ty = tid >> 4;
    const int ar = tid >> 2, ac4 = tid & 3;
    const int br = tid >> 6, bc2 = tid & 63;
    const float scale = 1.0f;
    const bool HAS_BIAS = false;
    const float* bias = nullptr;

    unsigned long long acc[8][4];
#pragma unroll
    for (int i = 0; i < 8; i++)
#pragma unroll
        for (int j = 0; j < 4; j++) acc[i][j] = 0ull;

    const float* Ap  = A + (size_t)(bm + ar) * lda + ac4 * 4;
    const float* Bpn = B + (size_t)br * ldb + bn + bc2 * 2;
    float4 ra0, ra1;
    float2 rbn[4];

#define LOADN(K0)                                                             \
    do {                                                                      \
        ra0 = __ldg((const float4*)(Ap + (K0)));                              \
        ra1 = __ldg((const float4*)(Ap + (size_t)64 * lda + (K0)));           \
        _Pragma("unroll")                                                     \
        for (int p = 0; p < 4; p++)                                           \
            rbn[p] = *(const float2*)(Bpn + (size_t)((K0) + p * 4) * ldb);    \
    } while (0)
#define STOREN(S)                                                             \
    do {                                                                      \
        As[S][ac4*4+0][ar] = ra0.x; As[S][ac4*4+1][ar] = ra0.y;               \
        As[S][ac4*4+2][ar] = ra0.z; As[S][ac4*4+3][ar] = ra0.w;               \
        As[S][ac4*4+0][ar+64] = ra1.x; As[S][ac4*4+1][ar+64] = ra1.y;         \
        As[S][ac4*4+2][ar+64] = ra1.z; As[S][ac4*4+3][ar+64] = ra1.w;         \
        _Pragma("unroll")                                                     \
        for (int p = 0; p < 4; p++) {                                         \
            Bs[S][br + p*4][bc2*2 + 0] = rbn[p].x;                            \
            Bs[S][br + p*4][bc2*2 + 1] = rbn[p].y;                            \
        }                                                                     \
    } while (0)

    LOADN(0);
    STOREN(0);
    __syncthreads();
    const int KT = Kd / 16;
#pragma unroll 1
    for (int kt = 0; kt < KT; kt++) {
        const int s = kt & 1;
        const bool more = (kt + 1) < KT;
        if (more) LOADN((kt + 1) * 16);
        MICRO_COMPUTE(s);
        if (more) { STOREN(s ^ 1); __syncthreads(); }
    }
    EPILOGUE();
#undef LOADN
#undef STOREN
}

// ---------------------------------------------------------------------------
// v[i] = c * sum_h K[i,h]*Wq[h,1024];  w[i] = c * sum_h K[i,h]*bq[h]
// ---------------------------------------------------------------------------
__global__ __launch_bounds__(256)
void vw_kernel(const float* __restrict__ Wq, const float* __restrict__ bq)
{
    __shared__ float scol[HID];
    __shared__ float sbq[HID];
    const int tid = threadIdx.x;
    for (int h = tid; h < HID; h += 256) {
        scol[h] = Wq[(size_t)h * LDQ + HID];
        sbq[h]  = bq[h];
    }
    __syncthreads();
    const int warp = tid >> 5, lane = tid & 31;
    const int row = blockIdx.x * 8 + warp;
    const float* Kr = g_K + (size_t)row * HID;
    float vv = 0.f, ww = 0.f;
#pragma unroll 4
    for (int m = 0; m < HID / 32; m++) {
        int h = lane + m * 32;
        float k = Kr[h];
        vv = fmaf(k, scol[h], vv);
        ww = fmaf(k, sbq[h], ww);
    }
#pragma unroll
    for (int off = 16; off; off >>= 1) {
        vv += __shfl_xor_sync(0xffffffffu, vv, off);
        ww += __shfl_xor_sync(0xffffffffu, ww, off);
    }
    if (lane == 0) { g_v[row] = COEF * vv; g_w[row] = COEF * ww; }
}

// ---------------------------------------------------------------------------
// Decoder helpers: SIGNED-order-preserving float<->int key.
// f >= 0: key = bits;  f < 0: key = bits ^ 0x7FFFFFFF.
// Verified monotone under signed compare:
//   -inf(0x807FFFFF) < -1(0xC07FFFFF) < -0(-1) < +0(0) < +1(0x3F800000) < +inf.
// ---------------------------------------------------------------------------
__device__ __forceinline__ int ordkey(float f) {
    int b = __float_as_int(f);
    return b ^ ((b >> 31) & 0x7FFFFFFF);
}
__device__ __forceinline__ float unord(int k) {
    int b = k ^ ((k >> 31) & 0x7FFFFFFF);   // same involution
    return __int_as_float(b);
}
__device__ __forceinline__ int redux_max_i32(int v) {
    int r;
    asm("redux.sync.max.s32 %0, %1, 0xffffffff;" : "=r"(r) : "r"(v));
    return r;
}

// ---------------------------------------------------------------------------
// Sequential decoder: 1 block x 256 threads, 8 candidates/thread.
// s = fmaf(u, v[i], P[last,i] + w[i])  -- EXACT R1 arithmetic.
// One barrier per step; per-thread v/w/demand hoisted to registers.
// ---------------------------------------------------------------------------
__global__ __launch_bounds__(256)
void decode_kernel(const float* __restrict__ demands,
                   const int* __restrict__ cap_ptr,
                   const int* __restrict__ depot_ptr,
                   float* __restrict__ out)
{
    __shared__ float sdem[N_NODES];
    __shared__ int2 red[2][8];

    const int tid = threadIdx.x;
    for (int i = tid; i < N_NODES; i += 256) sdem[i] = demands[i];

    // per-thread candidate block [tid*8, tid*8+8): loop-invariant data in regs
    float rv[8], rw[8], rd[8];
    {
        const float4* pv4 = (const float4*)(g_v + tid * 8);
        const float4* pw4 = (const float4*)(g_w + tid * 8);
        const float4* pd4 = (const float4*)(demands + tid * 8);
        float4 a, b;
        a = pv4[0]; b = pv4[1];
        rv[0]=a.x; rv[1]=a.y; rv[2]=a.z; rv[3]=a.w; rv[4]=b.x; rv[5]=b.y; rv[6]=b.z; rv[7]=b.w;
        a = pw4[0]; b = pw4[1];
        rw[0]=a.x; rw[1]=a.y; rw[2]=a.z; rw[3]=a.w; rw[4]=b.x; rw[5]=b.y; rw[6]=b.z; rw[7]=b.w;
        a = pd4[0]; b = pd4[1];
        rd[0]=a.x; rd[1]=a.y; rd[2]=a.z; rd[3]=a.w; rd[4]=b.x; rd[5]=b.y; rd[6]=b.z; rd[7]=b.w;
    }

    int ci = cap_ptr ? __ldg(cap_ptr) : 40;
    float cap = (ci >= 0 && ci < (1 << 23)) ? (float)ci : __int_as_float(ci);
    int depot = depot_ptr ? __ldg(depot_ptr) : 0;
    if ((unsigned)depot >= N_NODES) depot = 0;

    unsigned vis = 0;
    if ((depot >> 3) == tid) vis = 1u << (depot & 7);
    int last = depot;
    float load = cap;
    int count = 1;
    if (tid == 0) out[0] = (float)depot;
    __syncthreads();

    const int lane = tid & 31, warp = tid >> 5;
    int tstop = T_STEPS;

    for (int t = 0; t < T_STEPS; t++) {
        const float u = load / cap;
        const float4* Pr = (const float4*)(g_P + (size_t)last * N_NODES + tid * 8);
        float4 p0 = __ldg(Pr);
        float4 p1 = __ldg(Pr + 1);
        float pv[8] = {p0.x, p0.y, p0.z, p0.w, p1.x, p1.y, p1.z, p1.w};

        int bestk = KEY_SENTINEL, besti = tid * 8;
#pragma unroll
        for (int j = 0; j < 8; j++) {
            float s = fmaf(u, rv[j], pv[j] + rw[j]);   // exact R1 expression
            bool feas = !((vis >> j) & 1u) && (rd[j] <= load);
            int key = ordkey(s);
            if (feas && key > bestk) { bestk = key; besti = tid * 8 + j; }
        }
        int m = redux_max_i32(bestk);
        unsigned bal = __ballot_sync(0xffffffffu, bestk == m);
        int src = __ffs(bal) - 1;
        int wi = __shfl_sync(0xffffffffu, besti, src);
        if (lane == 0) red[t & 1][warp] = make_int2(m, wi);
        __syncthreads();

        int gk = red[t & 1][0].x, gi = red[t & 1][0].y;
#pragma unroll
        for (int w = 1; w < 8; w++) {
            int2 r = red[t & 1][w];
            if (r.x > gk) { gk = r.x; gi = r.y; }
        }
        if (gk > KEY_SENTINEL) {
            if (tid == 0) { out[1 + t] = (float)gi; out[TOUR_LEN + t] = unord(gk); }
            if ((gi >> 3) == tid) vis |= 1u << (gi & 7);
            load -= sdem[gi];
            last = gi;
            count++;
        } else {
            if (tid == 0) { out[1 + t] = (float)depot; out[TOUR_LEN + t] = 0.0f; }
            load = cap;
            last = depot;
            if (count == N_NODES) { tstop = t + 1; break; }
        }
    }
    for (int t2 = tstop + tid; t2 < T_STEPS; t2 += 256) {
        out[1 + t2] = (float)depot;
        out[TOUR_LEN + t2] = 0.0f;
    }
}

// ---------------------------------------------------------------------------
extern "C" void kernel_launch(void* const* d_in, const int* in_sizes, int n_in,
                              void* d_out, int out_size)
{
    const float* node_emb = (const float*)d_in[0];
    const float* demands  = (const float*)d_in[1];
    const float* Wq       = (const float*)d_in[2];
    const float* bq       = (const float*)d_in[3];
    const float* Wk       = (const float*)d_in[4];
    const float* bk       = (const float*)d_in[5];
    const int* capi = (n_in > 6) ? (const int*)d_in[6] : nullptr;
    const int* depi = (n_in > 7) ? (const int*)d_in[7] : nullptr;
    float* out = (float*)d_out;

    float *pK = nullptr, *pA = nullptr, *pP = nullptr;
    cudaGetSymbolAddress((void**)&pK, g_K);
    cudaGetSymbolAddress((void**)&pA, g_A);
    cudaGetSymbolAddress((void**)&pP, g_P);

    // K = E Wk^T + bk           [2048,1024]
    gemm_tn<true><<<dim3(HID / 128, N_NODES / 128), 256>>>(
        node_emb, Wk, bk, pK, HID, HID, HID, HID, 1.0f);
    // A = K @ Wq[:, :1024]      [2048,1024]
    gemm_nn<<<dim3(HID / 128, N_NODES / 128), 256>>>(
        pK, Wq, pA, HID, HID, LDQ, HID);
    // v, w (needs K)
    vw_kernel<<<N_NODES / 8, 256>>>(Wq, bq);
    // P = c * E A^T             [2048,2048]
    gemm_tn<false><<<dim3(N_NODES / 128, N_NODES / 128), 256>>>(
        node_emb, pA, nullptr, pP, HID, HID, HID, N_NODES, COEF);
    // sequential greedy decode
    decode_kernel<<<1, 256>>>(demands, capi, depi, out);

    (void)in_sizes; (void)out_size;
}